// round 1
// baseline (speedup 1.0000x reference)
#include <cuda_runtime.h>
#include <cstdint>

#define NR 131072
#define DD 128
#define KK 1024
#define TM 128
#define TK 128

typedef unsigned long long ull;

// ---- scratch (device globals; no allocation allowed) ----
__device__ int   g_idx[NR];
__device__ float g_sums[DD * KK];
__device__ float g_count[KK];
__device__ float g_lossb[256];
__device__ float g_eT[KK * DD];
__device__ float g_cnorm[KK];

// ---- f32x2 helpers (sm_103a packed fp32) ----
__device__ __forceinline__ ull dup2(float v) {
    ull r; unsigned u = __float_as_uint(v);
    asm("mov.b64 %0, {%1, %1};" : "=l"(r) : "r"(u));
    return r;
}
__device__ __forceinline__ void ffma2(ull& d, ull a, ull b) {
    asm("fma.rn.f32x2 %0, %1, %2, %0;" : "+l"(d) : "l"(a), "l"(b));
}
__device__ __forceinline__ float2 unpk(ull v) {
    unsigned lo, hi;
    asm("mov.b64 {%0, %1}, %2;" : "=r"(lo), "=r"(hi) : "l"(v));
    return make_float2(__uint_as_float(lo), __uint_as_float(hi));
}

// ---- prep kernels ----
__global__ void zero_kernel() {
    int i = blockIdx.x * 256 + threadIdx.x;
    if (i < DD * KK) g_sums[i] = 0.f;
    if (i < KK)      g_count[i] = 0.f;
    if (i < 256)     g_lossb[i] = 0.f;
}

__global__ void transpose_kernel(const float* __restrict__ emb) {
    __shared__ float t[32][33];
    int kb = blockIdx.x * 32, db = blockIdx.y * 32;
    int tx = threadIdx.x, ty = threadIdx.y;
    #pragma unroll
    for (int r = ty; r < 32; r += 8)
        t[r][tx] = emb[(size_t)(db + r) * KK + kb + tx];
    __syncthreads();
    #pragma unroll
    for (int r = ty; r < 32; r += 8)
        g_eT[(size_t)(kb + r) * DD + db + tx] = t[tx][r];
}

__global__ void cnorm_kernel(const float* __restrict__ emb) {
    int k = blockIdx.x * 256 + threadIdx.x;
    float s = 0.f;
    #pragma unroll 8
    for (int d = 0; d < DD; d++) {
        float e = emb[(size_t)d * KK + k];
        s = fmaf(e, e, s);
    }
    g_cnorm[k] = s;
}

// ---- fused distance-GEMM + argmin ----
// block: 256 threads, 128 rows x (8 tiles of 128 codes), 8x8 micro-tile/thread.
// dist proxy = ||e_k||^2 - 2 x.e_k   (||x||^2 constant per row, drops from argmin)
__global__ void __launch_bounds__(256, 1)
argmin_kernel(const float* __restrict__ x, const float* __restrict__ emb) {
    extern __shared__ float smem[];
    ull*   xsT = (ull*)smem;                 // [DD][TM] duplicated fp32 pairs (128KB)
    float* es  = (float*)(xsT + DD * TM);    // [DD][TK] (64KB)
    float* cs  = es + DD * TK;               // [TK]

    int tid = threadIdx.x;
    int tx = tid & 15, ty = tid >> 4;
    int row0 = blockIdx.x * TM;

    // load x tile, transposed + duplicated (L1 absorbs the strided reads; tile fits L1)
    #pragma unroll
    for (int it = 0; it < (TM * DD / 4) / 256; it++) {
        int i = it * 256 + tid;
        int d4 = i >> 7, r = i & (TM - 1);
        float4 v = *(const float4*)(x + (size_t)(row0 + r) * DD + d4 * 4);
        xsT[(4 * d4 + 0) * TM + r] = dup2(v.x);
        xsT[(4 * d4 + 1) * TM + r] = dup2(v.y);
        xsT[(4 * d4 + 2) * TM + r] = dup2(v.z);
        xsT[(4 * d4 + 3) * TM + r] = dup2(v.w);
    }

    float minv[8]; int mini[8];
    #pragma unroll
    for (int i = 0; i < 8; i++) { minv[i] = 3.4e38f; mini[i] = 0; }

    int r0 = ty * 8, c0 = tx * 8;

    for (int kt = 0; kt < KK / TK; kt++) {
        __syncthreads();
        int cg = kt * TK;
        // stream embeddings tile (coalesced; K-resident in L2)
        #pragma unroll
        for (int it = 0; it < (DD * TK / 4) / 256; it++) {
            int i = it * 256 + tid;
            int d = i >> 5, c4 = i & 31;
            *(float4*)(es + d * TK + c4 * 4) =
                *(const float4*)(emb + (size_t)d * KK + cg + c4 * 4);
        }
        if (tid < TK / 4)
            *(float4*)(cs + tid * 4) = *(const float4*)(g_cnorm + cg + tid * 4);
        __syncthreads();

        ull acc[8][4];
        #pragma unroll
        for (int i = 0; i < 8; i++)
            #pragma unroll
            for (int j = 0; j < 4; j++) acc[i][j] = 0ULL;

        #pragma unroll 8
        for (int d = 0; d < DD; d++) {
            ull a[8], b[4];
            const ull* ar = xsT + d * TM + r0;
            #pragma unroll
            for (int i = 0; i < 8; i++) a[i] = ar[i];
            const ull* br = (const ull*)(es + d * TK) + (c0 >> 1);
            #pragma unroll
            for (int j = 0; j < 4; j++) b[j] = br[j];
            #pragma unroll
            for (int i = 0; i < 8; i++)
                #pragma unroll
                for (int j = 0; j < 4; j++) ffma2(acc[i][j], a[i], b[j]);
        }

        // fold tile into running argmin (first-index tie-break, ascending order)
        #pragma unroll
        for (int i = 0; i < 8; i++) {
            #pragma unroll
            for (int j = 0; j < 4; j++) {
                float2 s = unpk(acc[i][j]);
                float dl = cs[c0 + 2 * j]     - 2.f * s.x;
                float dh = cs[c0 + 2 * j + 1] - 2.f * s.y;
                int il = cg + c0 + 2 * j;
                if (dl < minv[i]) { minv[i] = dl; mini[i] = il; }
                if (dh < minv[i]) { minv[i] = dh; mini[i] = il + 1; }
            }
        }
    }

    // reduce (val, idx) across the 16 tx lanes sharing each row
    #pragma unroll
    for (int i = 0; i < 8; i++) {
        float v = minv[i]; int ix = mini[i];
        #pragma unroll
        for (int off = 8; off; off >>= 1) {
            float ov = __shfl_down_sync(0xffffffffu, v, off, 16);
            int   oi = __shfl_down_sync(0xffffffffu, ix, off, 16);
            if (ov < v || (ov == v && oi < ix)) { v = ov; ix = oi; }
        }
        if (tx == 0) g_idx[row0 + r0 + i] = ix;
    }
}

// ---- gather q_st, commitment loss, segment sums ----
__global__ void scatter_kernel(const float* __restrict__ x, float* __restrict__ outq) {
    int gid = blockIdx.x * 256 + threadIdx.x;
    int n = gid >> 5, dq = gid & 31, d0 = dq * 4;
    int k = g_idx[n];
    float4 xv = *(const float4*)(x + (size_t)n * DD + d0);
    float4 qv = *(const float4*)(g_eT + (size_t)k * DD + d0);
    float r0 = qv.x - xv.x, r1 = qv.y - xv.y, r2 = qv.z - xv.z, r3 = qv.w - xv.w;
    float4 o = make_float4(xv.x + r0, xv.y + r1, xv.z + r2, xv.w + r3);
    *(float4*)(outq + (size_t)n * DD + d0) = o;
    float ls = r0 * r0 + r1 * r1 + r2 * r2 + r3 * r3;

    atomicAdd(&g_sums[(size_t)(d0 + 0) * KK + k], xv.x);
    atomicAdd(&g_sums[(size_t)(d0 + 1) * KK + k], xv.y);
    atomicAdd(&g_sums[(size_t)(d0 + 2) * KK + k], xv.z);
    atomicAdd(&g_sums[(size_t)(d0 + 3) * KK + k], xv.w);
    if (dq == 0) atomicAdd(&g_count[k], 1.0f);

    __shared__ float wsum[8];
    #pragma unroll
    for (int off = 16; off; off >>= 1) ls += __shfl_down_sync(0xffffffffu, ls, off);
    if ((threadIdx.x & 31) == 0) wsum[threadIdx.x >> 5] = ls;
    __syncthreads();
    if (threadIdx.x < 8) {
        float t = wsum[threadIdx.x];
        #pragma unroll
        for (int off = 4; off; off >>= 1) t += __shfl_down_sync(0xffu, t, off);
        if (threadIdx.x == 0) atomicAdd(&g_lossb[blockIdx.x & 255], t);
    }
}

// ---- EMA finalize + loss ----
__global__ void finalize_kernel(const float* __restrict__ ema_count,
                                const float* __restrict__ emb_sum,
                                float* __restrict__ out, long long out_size) {
    long long base_q = (long long)NR * DD;
    // expected layout: q_st | embeddings_new | ema_count_new | embeddings_sum_new | loss
    if (out_size < base_q + 2LL * DD * KK + KK + 1) return;
    int i = blockIdx.x * 256 + threadIdx.x;
    float* out_emb  = out + base_q;
    float* out_cnt  = out_emb + DD * KK;
    float* out_sum  = out_cnt + KK;
    float* out_loss = out_sum + DD * KK;
    if (i < DD * KK) {
        int k = i & (KK - 1);
        float cnt = 0.15f * ema_count[k] + 0.85f * g_count[k];
        float s   = 0.15f * emb_sum[i]   + 0.85f * g_sums[i];
        out_sum[i] = s;
        out_emb[i] = s / fmaxf(cnt, 1e-5f);
    }
    if (i < KK) out_cnt[i] = 0.15f * ema_count[i] + 0.85f * g_count[i];
    if (i == 0) {
        float t = 0.f;
        for (int b = 0; b < 256; b++) t += g_lossb[b];
        *out_loss = t * (1.0f / ((float)NR * (float)DD));
    }
}

extern "C" void kernel_launch(void* const* d_in, const int* in_sizes, int n_in,
                              void* d_out, int out_size) {
    const float* x         = (const float*)d_in[0];
    const float* emb       = (const float*)d_in[1];
    const float* ema_count = (const float*)d_in[2];
    const float* emb_sum   = (const float*)d_in[3];
    float* out = (float*)d_out;

    size_t smem = (size_t)DD * TM * 8 + (size_t)DD * TK * 4 + TK * 4; // 197120 B
    cudaFuncSetAttribute(argmin_kernel,
                         cudaFuncAttributeMaxDynamicSharedMemorySize, (int)smem);

    zero_kernel<<<(DD * KK + 255) / 256, 256>>>();
    transpose_kernel<<<dim3(KK / 32, DD / 32), dim3(32, 8)>>>(emb);
    cnorm_kernel<<<KK / 256, 256>>>(emb);
    argmin_kernel<<<NR / TM, 256, smem>>>(x, emb);
    scatter_kernel<<<(NR * 32) / 256, 256>>>(x, out);
    finalize_kernel<<<(DD * KK + 255) / 256, 256>>>(ema_count, emb_sum, out,
                                                    (long long)out_size);
}

// round 3
// speedup vs baseline: 1.9048x; 1.9048x over previous
#include <cuda_runtime.h>
#include <cuda_bf16.h>
#include <cstdint>

#define NR 131072
#define DD 128
#define KK 1024
#define TM 128
#define PAD 136                 // bf16 elems per padded row (272 B) -> conflict-free LDS

typedef unsigned long long ull;

// ---------------- device scratch (static; no runtime alloc) ----------------
__device__ int   g_idx[NR];
__device__ float g_sums[DD * KK];
__device__ float g_count[KK];
__device__ float g_lossb[256];
__device__ float g_eT[KK * DD];        // e^T [K][D] fp32
__device__ __nv_bfloat16 g_eThi[KK * DD];
__device__ __nv_bfloat16 g_eTlo[KK * DD];
__device__ float g_cnorm[KK];
__device__ int   g_nflag;
__device__ int   g_flag[NR];

// ---------------- smem layout (bytes) ----------------
#define AHALF   34816            /* 128*PAD*2 */
#define SM_A    0                /* Ahi | Alo : 69632 */
#define SM_B0   69632            /* Bhi | Blo : 69632 */
#define SM_B1   139264
#define SM_CN   208896           /* 1024 fp32 */
#define SM_TOTAL 212992

#define TAU_D 1.5e-2f            // flag threshold on D-gap (dist-gap = 2*TAU_D)

// ---------------- helpers ----------------
__device__ __forceinline__ uint32_t smem_u32(const void* p) {
    uint32_t a;
    asm("{ .reg .u64 t; cvta.to.shared.u64 t, %1; cvt.u32.u64 %0, t; }"
        : "=r"(a) : "l"(p));
    return a;
}
__device__ __forceinline__ void cp_async16(uint32_t dst, const void* src) {
    asm volatile("cp.async.cg.shared.global [%0], [%1], 16;"
                 :: "r"(dst), "l"(src) : "memory");
}
__device__ __forceinline__ void cp_commit() {
    asm volatile("cp.async.commit_group;" ::: "memory");
}
__device__ __forceinline__ void cp_wait0() {
    asm volatile("cp.async.wait_group 0;" ::: "memory");
}
__device__ __forceinline__ void mma_bf16(float& d0, float& d1, float& d2, float& d3,
                                         uint32_t a0, uint32_t a1, uint32_t a2, uint32_t a3,
                                         uint32_t b0, uint32_t b1) {
    asm volatile("mma.sync.aligned.m16n8k16.row.col.f32.bf16.bf16.f32 "
                 "{%0,%1,%2,%3}, {%4,%5,%6,%7}, {%8,%9}, {%0,%1,%2,%3};"
                 : "+f"(d0), "+f"(d1), "+f"(d2), "+f"(d3)
                 : "r"(a0), "r"(a1), "r"(a2), "r"(a3), "r"(b0), "r"(b1));
}

// ---------------- prep kernels ----------------
__global__ void zero_kernel() {
    int i = blockIdx.x * 256 + threadIdx.x;
    if (i < DD * KK) g_sums[i] = 0.f;
    if (i < KK)      g_count[i] = 0.f;
    if (i < 256)     g_lossb[i] = 0.f;
    if (i == 0)      g_nflag = 0;
}

__global__ void transpose_kernel(const float* __restrict__ emb) {
    __shared__ float t[32][33];
    int kb = blockIdx.x * 32, db = blockIdx.y * 32;
    int tx = threadIdx.x, ty = threadIdx.y;
    #pragma unroll
    for (int r = ty; r < 32; r += 8)
        t[r][tx] = emb[(size_t)(db + r) * KK + kb + tx];
    __syncthreads();
    #pragma unroll
    for (int r = ty; r < 32; r += 8)
        g_eT[(size_t)(kb + r) * DD + db + tx] = t[tx][r];
}

__global__ void esplit_kernel() {
    int i = blockIdx.x * 256 + threadIdx.x;   // KK*DD = 131072
    float v = g_eT[i];
    __nv_bfloat16 h = __float2bfloat16(v);
    g_eThi[i] = h;
    g_eTlo[i] = __float2bfloat16(v - __bfloat162float(h));
}

__global__ void cnorm_kernel(const float* __restrict__ emb) {
    int k = blockIdx.x * 256 + threadIdx.x;
    float s = 0.f;
    #pragma unroll 8
    for (int d = 0; d < DD; d++) {
        float e = emb[(size_t)d * KK + k];
        s = fmaf(e, e, s);
    }
    g_cnorm[k] = s;
}

// ---------------- HMMA bf16-split argmin ----------------
// block = 256 threads / 8 warps; 128 rows; 8 tiles of 128 codes.
// warp w owns rows w*16 .. w*16+15; per tile 16 m16n8 fragments.
// D = sim - cn/2  (acc init = -cn/2)  =>  dist = -2*D  =>  argmin dist == argmax D.
__global__ void __launch_bounds__(256, 1)
argmin_mma_kernel(const float* __restrict__ x) {
    extern __shared__ __align__(16) char smem[];
    const int tid = threadIdx.x;
    const int wid = tid >> 5, lane = tid & 31;
    const int g = lane >> 2, tg = lane & 3;
    const int row0 = blockIdx.x * TM;
    const uint32_t sb = smem_u32(smem);

    // ---- A tile: load fp32 x, split to bf16 hi/lo, store padded ----
    #pragma unroll
    for (int it = 0; it < 8; it++) {
        int c = it * 256 + tid;            // 0..2047
        int r = c >> 4, c8 = c & 15;
        const float4* src = (const float4*)(x + (size_t)(row0 + r) * DD + c8 * 8);
        float4 a = src[0], b = src[1];
        float vals[8] = {a.x, a.y, a.z, a.w, b.x, b.y, b.z, b.w};
        unsigned hs[8], ls[8];
        #pragma unroll
        for (int j = 0; j < 8; j++) {
            __nv_bfloat16 hb = __float2bfloat16(vals[j]);
            hs[j] = __bfloat16_as_ushort(hb);
            ls[j] = __bfloat16_as_ushort(__float2bfloat16(vals[j] - __bfloat162float(hb)));
        }
        uint4 ph, pl;
        ph.x = hs[0] | (hs[1] << 16); ph.y = hs[2] | (hs[3] << 16);
        ph.z = hs[4] | (hs[5] << 16); ph.w = hs[6] | (hs[7] << 16);
        pl.x = ls[0] | (ls[1] << 16); pl.y = ls[2] | (ls[3] << 16);
        pl.z = ls[4] | (ls[5] << 16); pl.w = ls[6] | (ls[7] << 16);
        int off = r * (PAD * 2) + c8 * 16;
        *(uint4*)(smem + SM_A + off)         = ph;
        *(uint4*)(smem + SM_A + AHALF + off) = pl;
    }
    // cnorm -> smem
    ((float4*)(smem + SM_CN))[tid] = ((const float4*)g_cnorm)[tid];

    // ---- B tile 0 via cp.async ----
    {
        #pragma unroll
        for (int it = 0; it < 16; it++) {
            int i = it * 256 + tid;        // 0..4095
            int half = i >> 11, r = (i >> 4) & 127, c8 = i & 15;
            const __nv_bfloat16* src =
                (half ? g_eTlo : g_eThi) + (size_t)r * DD + c8 * 8;
            cp_async16(sb + SM_B0 + half * AHALF + r * (PAD * 2) + c8 * 16, src);
        }
        cp_commit();
    }
    cp_wait0();
    __syncthreads();

    // per-thread running best (rows rw+g and rw+g+8)
    float va1 = -3.4e38f, va2 = -3.4e38f, vb1 = -3.4e38f, vb2 = -3.4e38f;
    int ia1 = 0, ib1 = 0;
    const int rw = wid * 16;
    const float* cns = (const float*)(smem + SM_CN);

    for (int t = 0; t < 8; t++) {
        const int cur = t & 1;
        // prefetch next tile
        if (t < 7) {
            int nb = cur ^ 1;
            #pragma unroll
            for (int it = 0; it < 16; it++) {
                int i = it * 256 + tid;
                int half = i >> 11, r = (i >> 4) & 127, c8 = i & 15;
                const __nv_bfloat16* src =
                    (half ? g_eTlo : g_eThi) + (size_t)((t + 1) * 128 + r) * DD + c8 * 8;
                cp_async16(sb + (nb ? SM_B1 : SM_B0) + half * AHALF + r * (PAD * 2) + c8 * 16, src);
            }
            cp_commit();
        }

        const char* Bhi = smem + (cur ? SM_B1 : SM_B0);
        const char* Blo = Bhi + AHALF;
        const char* Ahi = smem + SM_A;
        const char* Alo = Ahi + AHALF;

        // init accumulators to -cn/2
        float acc[16][4];
        #pragma unroll
        for (int f = 0; f < 16; f++) {
            float c0 = -0.5f * cns[t * 128 + f * 8 + tg * 2];
            float c1 = -0.5f * cns[t * 128 + f * 8 + tg * 2 + 1];
            acc[f][0] = c0; acc[f][1] = c1; acc[f][2] = c0; acc[f][3] = c1;
        }

        #pragma unroll
        for (int k = 0; k < 8; k++) {
            int ca = k * 16 + tg * 2;
            int oa0 = (rw + g) * (PAD * 2) + ca * 2;
            int oa1 = (rw + g + 8) * (PAD * 2) + ca * 2;
            uint32_t ah0 = *(const uint32_t*)(Ahi + oa0);
            uint32_t ah1 = *(const uint32_t*)(Ahi + oa1);
            uint32_t ah2 = *(const uint32_t*)(Ahi + oa0 + 16);
            uint32_t ah3 = *(const uint32_t*)(Ahi + oa1 + 16);
            uint32_t al0 = *(const uint32_t*)(Alo + oa0);
            uint32_t al1 = *(const uint32_t*)(Alo + oa1);
            uint32_t al2 = *(const uint32_t*)(Alo + oa0 + 16);
            uint32_t al3 = *(const uint32_t*)(Alo + oa1 + 16);
            #pragma unroll
            for (int f = 0; f < 16; f++) {
                int ob = (f * 8 + g) * (PAD * 2) + ca * 2;
                uint32_t bh0 = *(const uint32_t*)(Bhi + ob);
                uint32_t bh1 = *(const uint32_t*)(Bhi + ob + 16);
                uint32_t bl0 = *(const uint32_t*)(Blo + ob);
                uint32_t bl1 = *(const uint32_t*)(Blo + ob + 16);
                mma_bf16(acc[f][0], acc[f][1], acc[f][2], acc[f][3],
                         ah0, ah1, ah2, ah3, bh0, bh1);
                mma_bf16(acc[f][0], acc[f][1], acc[f][2], acc[f][3],
                         ah0, ah1, ah2, ah3, bl0, bl1);
                mma_bf16(acc[f][0], acc[f][1], acc[f][2], acc[f][3],
                         al0, al1, al2, al3, bh0, bh1);
            }
        }

        // fold into running max-D trackers
        #pragma unroll
        for (int f = 0; f < 16; f++) {
            int idx0 = t * 128 + f * 8 + tg * 2;
            float d;
            d = acc[f][0];
            if (d > va1) { va2 = va1; va1 = d; ia1 = idx0; } else if (d > va2) va2 = d;
            d = acc[f][1];
            if (d > va1) { va2 = va1; va1 = d; ia1 = idx0 + 1; } else if (d > va2) va2 = d;
            d = acc[f][2];
            if (d > vb1) { vb2 = vb1; vb1 = d; ib1 = idx0; } else if (d > vb2) vb2 = d;
            d = acc[f][3];
            if (d > vb1) { vb2 = vb1; vb1 = d; ib1 = idx0 + 1; } else if (d > vb2) vb2 = d;
        }

        if (t < 7) cp_wait0();
        __syncthreads();
    }

    // reduce across the 4 tg-lanes sharing each row (segments of width 4)
    #pragma unroll
    for (int off = 2; off; off >>= 1) {
        float ov1 = __shfl_down_sync(0xffffffffu, va1, off, 4);
        int   oi1 = __shfl_down_sync(0xffffffffu, ia1, off, 4);
        float ov2 = __shfl_down_sync(0xffffffffu, va2, off, 4);
        if (ov1 > va1 || (ov1 == va1 && oi1 < ia1)) {
            va2 = fmaxf(va1, ov2); va1 = ov1; ia1 = oi1;
        } else va2 = fmaxf(va2, ov1);
        ov1 = __shfl_down_sync(0xffffffffu, vb1, off, 4);
        oi1 = __shfl_down_sync(0xffffffffu, ib1, off, 4);
        ov2 = __shfl_down_sync(0xffffffffu, vb2, off, 4);
        if (ov1 > vb1 || (ov1 == vb1 && oi1 < ib1)) {
            vb2 = fmaxf(vb1, ov2); vb1 = ov1; ib1 = oi1;
        } else vb2 = fmaxf(vb2, ov1);
    }
    if (tg == 0) {
        int ra = row0 + rw + g, rb = ra + 8;
        g_idx[ra] = ia1;
        g_idx[rb] = ib1;
        if (va1 - va2 < TAU_D) { int s = atomicAdd(&g_nflag, 1); g_flag[s] = ra; }
        if (vb1 - vb2 < TAU_D) { int s = atomicAdd(&g_nflag, 1); g_flag[s] = rb; }
    }
}

// ---------------- exact fp32 rescore of flagged rows ----------------
__global__ void rescore_kernel(const float* __restrict__ x) {
    __shared__ float xs[8 * 128];
    __shared__ ull best[8];
    __shared__ int rows[8];
    int tid = threadIdx.x;
    int nflag = g_nflag;
    for (int base = blockIdx.x * 8; base < nflag; base += gridDim.x * 8) {
        int cnt = min(8, nflag - base);
        if (tid < cnt) { rows[tid] = g_flag[base + tid]; best[tid] = ~0ull; }
        __syncthreads();
        for (int i = tid; i < cnt * 128; i += 256)
            xs[i] = x[(size_t)rows[i >> 7] * DD + (i & 127)];
        __syncthreads();
        for (int k = tid; k < KK; k += 256) {
            float s[8];
            #pragma unroll
            for (int i = 0; i < 8; i++) s[i] = 0.f;
            const float4* e4 = (const float4*)(g_eT + (size_t)k * DD);
            const float4* x4 = (const float4*)xs;
            #pragma unroll 4
            for (int d4 = 0; d4 < 32; d4++) {
                float4 e = e4[d4];
                #pragma unroll
                for (int i = 0; i < 8; i++) {
                    float4 xv = x4[i * 32 + d4];
                    s[i] = fmaf(e.x, xv.x, s[i]);
                    s[i] = fmaf(e.y, xv.y, s[i]);
                    s[i] = fmaf(e.z, xv.z, s[i]);
                    s[i] = fmaf(e.w, xv.w, s[i]);
                }
            }
            float cn = g_cnorm[k];
            #pragma unroll
            for (int i = 0; i < 8; i++) {
                float dist = fmaf(-2.f, s[i], cn);
                unsigned u = __float_as_uint(dist);
                u ^= (u >> 31) ? 0xFFFFFFFFu : 0x80000000u;
                ull key = ((ull)u << 32) | (unsigned)k;
                atomicMin(&best[i], key);
            }
        }
        __syncthreads();
        if (tid < cnt) g_idx[rows[tid]] = (int)(best[tid] & 0xFFFFFFFFu);
        __syncthreads();
    }
}

// ---------------- gather q_st, loss, segment sums ----------------
__global__ void scatter_kernel(const float* __restrict__ x, float* __restrict__ outq) {
    int gid = blockIdx.x * 256 + threadIdx.x;
    int n = gid >> 5, dq = gid & 31, d0 = dq * 4;
    int k = g_idx[n];
    float4 xv = *(const float4*)(x + (size_t)n * DD + d0);
    float4 qv = *(const float4*)(g_eT + (size_t)k * DD + d0);
    float r0 = qv.x - xv.x, r1 = qv.y - xv.y, r2 = qv.z - xv.z, r3 = qv.w - xv.w;
    float4 o = make_float4(xv.x + r0, xv.y + r1, xv.z + r2, xv.w + r3);
    *(float4*)(outq + (size_t)n * DD + d0) = o;
    float ls = r0 * r0 + r1 * r1 + r2 * r2 + r3 * r3;

    atomicAdd(&g_sums[(size_t)(d0 + 0) * KK + k], xv.x);
    atomicAdd(&g_sums[(size_t)(d0 + 1) * KK + k], xv.y);
    atomicAdd(&g_sums[(size_t)(d0 + 2) * KK + k], xv.z);
    atomicAdd(&g_sums[(size_t)(d0 + 3) * KK + k], xv.w);
    if (dq == 0) atomicAdd(&g_count[k], 1.0f);

    __shared__ float wsum[8];
    #pragma unroll
    for (int off = 16; off; off >>= 1) ls += __shfl_down_sync(0xffffffffu, ls, off);
    if ((threadIdx.x & 31) == 0) wsum[threadIdx.x >> 5] = ls;
    __syncthreads();
    if (threadIdx.x < 8) {
        float t = wsum[threadIdx.x];
        #pragma unroll
        for (int off = 4; off; off >>= 1) t += __shfl_down_sync(0xffu, t, off);
        if (threadIdx.x == 0) atomicAdd(&g_lossb[blockIdx.x & 255], t);
    }
}

// ---------------- EMA finalize + loss ----------------
__global__ void finalize_kernel(const float* __restrict__ ema_count,
                                const float* __restrict__ emb_sum,
                                float* __restrict__ out, long long out_size) {
    long long base_q = (long long)NR * DD;
    if (out_size < base_q + 2LL * DD * KK + KK + 1) return;
    int i = blockIdx.x * 256 + threadIdx.x;
    float* out_emb  = out + base_q;
    float* out_cnt  = out_emb + DD * KK;
    float* out_sum  = out_cnt + KK;
    float* out_loss = out_sum + DD * KK;
    if (i < DD * KK) {
        int k = i & (KK - 1);
        float cnt = 0.15f * ema_count[k] + 0.85f * g_count[k];
        float s   = 0.15f * emb_sum[i]   + 0.85f * g_sums[i];
        out_sum[i] = s;
        out_emb[i] = s / fmaxf(cnt, 1e-5f);
    }
    if (i < KK) out_cnt[i] = 0.15f * ema_count[i] + 0.85f * g_count[i];
    if (i == 0) {
        float t = 0.f;
        for (int b = 0; b < 256; b++) t += g_lossb[b];
        *out_loss = t * (1.0f / ((float)NR * (float)DD));
    }
}

extern "C" void kernel_launch(void* const* d_in, const int* in_sizes, int n_in,
                              void* d_out, int out_size) {
    const float* x         = (const float*)d_in[0];
    const float* emb       = (const float*)d_in[1];
    const float* ema_count = (const float*)d_in[2];
    const float* emb_sum   = (const float*)d_in[3];
    float* out = (float*)d_out;

    cudaFuncSetAttribute(argmin_mma_kernel,
                         cudaFuncAttributeMaxDynamicSharedMemorySize, SM_TOTAL);

    zero_kernel<<<(DD * KK + 255) / 256, 256>>>();
    transpose_kernel<<<dim3(KK / 32, DD / 32), dim3(32, 8)>>>(emb);
    cnorm_kernel<<<KK / 256, 256>>>(emb);
    esplit_kernel<<<KK * DD / 256, 256>>>();
    argmin_mma_kernel<<<NR / TM, 256, SM_TOTAL>>>(x);
    rescore_kernel<<<128, 256>>>(x);
    scatter_kernel<<<(NR * 32) / 256, 256>>>(x, out);
    finalize_kernel<<<(DD * KK + 255) / 256, 256>>>(ema_count, emb_sum, out,
                                                    (long long)out_size);
}